// round 5
// baseline (speedup 1.0000x reference)
#include <cuda_runtime.h>
#include <stdint.h>

#define BATCH    16
#define NBOX     4096
#define NCLS     80
#define MAX_DET  100
#define IOU_THR  0.5f
#define CONF_THR 0.5f
#define FULL     0xffffffffu
#define THREADS  1024
#define PER      (NBOX / THREADS)   // 4 keys+boxes per thread

// scratch: per-row sort keys  (score_bits << 32) | (0xFFFFFFFF - idx)
__device__ unsigned long long g_keys[BATCH * NBOX];

// ---------------------------------------------------------------------------
// Kernel 1: softmax(square(x*10)) per row, write cls_predictions, emit keys.
// ---------------------------------------------------------------------------
__global__ void __launch_bounds__(256)
softmax_key_kernel(const float* __restrict__ cls_in,
                   float* __restrict__ cls_out,
                   unsigned long long* __restrict__ keys)
{
    const int lane = threadIdx.x & 31;
    const int row  = blockIdx.x * (blockDim.x >> 5) + (threadIdx.x >> 5);
    if (row >= BATCH * NBOX) return;

    const float* in = cls_in + (size_t)row * NCLS;

    const bool has2 = lane < (NCLS - 64);
    float x0 = in[lane]      * 10.0f;
    float x1 = in[lane + 32] * 10.0f;
    float x2 = has2 ? in[lane + 64] * 10.0f : 0.0f;
    float a0 = x0 * x0, a1 = x1 * x1, a2 = x2 * x2;

    float amax = fmaxf(a0, a1);
    if (has2) amax = fmaxf(amax, a2);
    #pragma unroll
    for (int o = 16; o; o >>= 1)
        amax = fmaxf(amax, __shfl_xor_sync(FULL, amax, o));

    float e0 = expf(a0 - amax);
    float e1 = expf(a1 - amax);
    float e2 = has2 ? expf(a2 - amax) : 0.0f;

    float s = e0 + e1 + e2;
    #pragma unroll
    for (int o = 16; o; o >>= 1)
        s += __shfl_xor_sync(FULL, s, o);

    const float recip = 1.0f / s;
    float o0 = e0 * recip, o1 = e1 * recip, o2 = e2 * recip;

    float* out = cls_out + (size_t)row * NCLS;
    out[lane]      = o0;
    out[lane + 32] = o1;
    if (has2) out[lane + 64] = o2;

    float m = fmaxf(o0, o1);
    if (has2) m = fmaxf(m, o2);
    #pragma unroll
    for (int o = 16; o; o >>= 1)
        m = fmaxf(m, __shfl_xor_sync(FULL, m, o));

    if (lane == 0) {
        const unsigned n = (unsigned)(row & (NBOX - 1));
        keys[row] = ((unsigned long long)__float_as_uint(m) << 32)
                  | (unsigned long long)(0xffffffffu - n);
    }
}

// ---------------------------------------------------------------------------
// Kernel 2: per-batch iterative argmax + suppress (no sort).
// Keys + boxes register-resident; one barrier per round (<=100 rounds).
// Dynamic smem: float4 sbox[NBOX] | float sarea[NBOX]   (80KB)
// ---------------------------------------------------------------------------
__global__ void __launch_bounds__(THREADS, 1)
nms_kernel(const float* __restrict__ boxes,        // [B,N,4]
           const float* __restrict__ cls_soft,     // [B,N,C]
           const unsigned long long* __restrict__ keys,
           float* __restrict__ nms_box,            // [B,MAX_DET,4]
           float* __restrict__ nms_cls)            // [B,MAX_DET,C]
{
    extern __shared__ char dyn[];
    float4* sbox  = (float4*)dyn;                  // 64KB (normalized boxes)
    float*  sarea = (float*)(sbox + NBOX);         // 16KB

    __shared__ unsigned long long part[2][32];     // double-buffered partials
    __shared__ int kidx[MAX_DET];

    const int b    = blockIdx.x;
    const int tid  = threadIdx.x;
    const int lane = tid & 31;
    const int warp = tid >> 5;

    // ---- register-resident candidate state ----
    unsigned long long key[PER];
    float by1[PER], bx1[PER], by2[PER], bx2[PER], bar_[PER];

    const float4* bb4 = (const float4*)(boxes + (size_t)b * NBOX * 4);
    const unsigned long long* kg = keys + b * NBOX;
    #pragma unroll
    for (int s = 0; s < PER; s++) {
        const int i = tid + s * THREADS;
        key[s] = kg[i];
        float4 r = bb4[i];
        float y1 = fminf(r.x, r.z), y2 = fmaxf(r.x, r.z);
        float x1 = fminf(r.y, r.w), x2 = fmaxf(r.y, r.w);
        by1[s] = y1; bx1[s] = x1; by2[s] = y2; bx2[s] = x2;
        float a = (y2 - y1) * (x2 - x1);
        bar_[s] = a;
        sbox[i]  = make_float4(y1, x1, y2, x2);
        sarea[i] = a;
        // (sbox/sarea writes ordered before first read by round-0 barrier)
    }

    // ---- iterative argmax + suppress: exactly greedy NMS ----
    int count = 0;
    for (int round = 0; round < MAX_DET; round++) {
        // local max of my 4 keys
        unsigned long long m = key[0];
        #pragma unroll
        for (int s = 1; s < PER; s++) m = (key[s] > m) ? key[s] : m;
        // warp max
        #pragma unroll
        for (int o = 16; o; o >>= 1) {
            unsigned long long w = __shfl_xor_sync(FULL, m, o);
            m = (w > m) ? w : m;
        }
        if (lane == 0) part[round & 1][warp] = m;
        __syncthreads();                              // one barrier per round
        // every thread reduces the 32 partials
        unsigned long long wk = part[round & 1][0];
        #pragma unroll
        for (int j = 1; j < 32; j++) {
            unsigned long long w = part[round & 1][j];
            wk = (w > wk) ? w : wk;
        }

        const float wscore = __uint_as_float((unsigned)(wk >> 32));
        if (!(wscore > CONF_THR)) break;              // no more valid keeps
        const int widx = (int)(0xffffffffu - (unsigned)wk);

        const float4 wb = sbox[widx];                 // smem broadcast
        const float  wa = sarea[widx];
        if (tid == 0) kidx[count] = widx;
        count++;

        // suppress in registers (divide form identical to reference)
        #pragma unroll
        for (int s = 0; s < PER; s++) {
            if (key[s]) {
                float ih = fmaxf(0.0f, fminf(wb.z, by2[s]) - fmaxf(wb.x, by1[s]));
                float iw = fmaxf(0.0f, fminf(wb.w, bx2[s]) - fmaxf(wb.y, bx1[s]));
                float inter = ih * iw;
                float uni   = wa + bar_[s] - inter;
                float iou   = (inter > 0.0f) ? inter / uni : 0.0f;
                if (iou > IOU_THR || key[s] == wk) key[s] = 0ull;
            }
        }
    }
    __syncthreads();

    // ---- outputs (zero-pad beyond count) ----
    float* ob = nms_box + (size_t)b * MAX_DET * 4;
    for (int t = tid; t < MAX_DET * 4; t += blockDim.x) {
        int k = t >> 2, c = t & 3;
        ob[t] = (k < count)
              ? boxes[(size_t)b * NBOX * 4 + (size_t)kidx[k] * 4 + c]
              : 0.0f;
    }
    float* oc = nms_cls + (size_t)b * MAX_DET * NCLS;
    for (int t = tid; t < MAX_DET * NCLS; t += blockDim.x) {
        int k = t / NCLS, c = t % NCLS;
        oc[t] = (k < count)
              ? cls_soft[((size_t)b * NBOX + (size_t)kidx[k]) * NCLS + c]
              : 0.0f;
    }
}

// ---------------------------------------------------------------------------
extern "C" void kernel_launch(void* const* d_in, const int* in_sizes, int n_in,
                              void* d_out, int out_size)
{
    const float* boxes;
    const float* cls;
    if (in_sizes[0] == BATCH * NBOX * 4) {
        boxes = (const float*)d_in[0];
        cls   = (const float*)d_in[1];
    } else {
        boxes = (const float*)d_in[1];
        cls   = (const float*)d_in[0];
    }

    float* out      = (float*)d_out;
    float* nms_box  = out;                                  // [16,100,4]
    float* nms_cls  = out + BATCH * MAX_DET * 4;            // [16,100,80]
    float* cls_pred = out + BATCH * MAX_DET * 4
                          + BATCH * MAX_DET * NCLS;         // [16,4096,80]

    unsigned long long* keys = nullptr;
    cudaGetSymbolAddress((void**)&keys, g_keys);

    const int DYN_SMEM = NBOX * (int)sizeof(float4)
                       + NBOX * (int)sizeof(float);         // 80 KB
    static int smem_set = 0;
    if (!smem_set) {
        cudaFuncSetAttribute(nms_kernel,
                             cudaFuncAttributeMaxDynamicSharedMemorySize,
                             DYN_SMEM);
        smem_set = 1;
    }

    const int rows = BATCH * NBOX;
    softmax_key_kernel<<<rows / 8, 256>>>(cls, cls_pred, keys);
    nms_kernel<<<BATCH, THREADS, DYN_SMEM>>>(boxes, cls_pred, keys, nms_box, nms_cls);
}

// round 6
// speedup vs baseline: 2.0888x; 2.0888x over previous
#include <cuda_runtime.h>
#include <stdint.h>

#define BATCH    16
#define NBOX     4096
#define NCLS     80
#define MAX_DET  100
#define IOU_THR  0.5f
#define CONF_THR 0.5f
#define FULL     0xffffffffu
#define CHUNK    256

// scratch: per-row sort keys  (score_bits << 32) | (0xFFFFFFFF - idx)
__device__ unsigned long long g_keys[BATCH * NBOX];

// ---------------------------------------------------------------------------
// Kernel 1: softmax(square(x*10)) per row, write cls_predictions, emit keys.
// ---------------------------------------------------------------------------
__global__ void __launch_bounds__(256)
softmax_key_kernel(const float* __restrict__ cls_in,
                   float* __restrict__ cls_out,
                   unsigned long long* __restrict__ keys)
{
    const int lane = threadIdx.x & 31;
    const int row  = blockIdx.x * (blockDim.x >> 5) + (threadIdx.x >> 5);
    if (row >= BATCH * NBOX) return;

    const float* in = cls_in + (size_t)row * NCLS;

    const bool has2 = lane < (NCLS - 64);
    float x0 = in[lane]      * 10.0f;
    float x1 = in[lane + 32] * 10.0f;
    float x2 = has2 ? in[lane + 64] * 10.0f : 0.0f;
    float a0 = x0 * x0, a1 = x1 * x1, a2 = x2 * x2;

    float amax = fmaxf(a0, a1);
    if (has2) amax = fmaxf(amax, a2);
    #pragma unroll
    for (int o = 16; o; o >>= 1)
        amax = fmaxf(amax, __shfl_xor_sync(FULL, amax, o));

    float e0 = expf(a0 - amax);
    float e1 = expf(a1 - amax);
    float e2 = has2 ? expf(a2 - amax) : 0.0f;

    float s = e0 + e1 + e2;
    #pragma unroll
    for (int o = 16; o; o >>= 1)
        s += __shfl_xor_sync(FULL, s, o);

    const float recip = 1.0f / s;
    float o0 = e0 * recip, o1 = e1 * recip, o2 = e2 * recip;

    float* out = cls_out + (size_t)row * NCLS;
    out[lane]      = o0;
    out[lane + 32] = o1;
    if (has2) out[lane + 64] = o2;

    float m = fmaxf(o0, o1);
    if (has2) m = fmaxf(m, o2);
    #pragma unroll
    for (int o = 16; o; o >>= 1)
        m = fmaxf(m, __shfl_xor_sync(FULL, m, o));

    if (lane == 0) {
        const unsigned n = (unsigned)(row & (NBOX - 1));
        keys[row] = ((unsigned long long)__float_as_uint(m) << 32)
                  | (unsigned long long)(0xffffffffu - n);
    }
}

// ---------------------------------------------------------------------------
// Kernel 2: sort + chunked NMS.
//   check phase : all 1024 threads, 4 per candidate, fixed-trip loop
//   resolve     : warp 0, work proportional to survivors only
// Dynamic smem: float4 sbox[NBOX] | u64 sk[NBOX] | float sarea[NBOX]  (112KB)
// ---------------------------------------------------------------------------
__global__ void __launch_bounds__(1024, 1)
nms_kernel(const float* __restrict__ boxes,        // [B,N,4]
           const float* __restrict__ cls_soft,     // [B,N,C]
           const unsigned long long* __restrict__ keys,
           float* __restrict__ nms_box,            // [B,MAX_DET,4]
           float* __restrict__ nms_cls)            // [B,MAX_DET,C]
{
    extern __shared__ char dyn[];
    float4*             sbox  = (float4*)dyn;                       // 64KB
    unsigned long long* sk    = (unsigned long long*)(sbox + NBOX); // 32KB
    float*              sarea = (float*)(sk + NBOX);                // 16KB

    __shared__ float4        kbox[MAX_DET];   // kept boxes (prev chunks)
    __shared__ float         kar[MAX_DET];
    __shared__ int           kidx[MAX_DET];
    __shared__ unsigned char ssup[CHUNK];
    __shared__ int s_count, s_stop;

    const int b    = blockIdx.x;
    const int tid  = threadIdx.x;
    const int lane = tid & 31;
    const int warp = tid >> 5;
    const int nwarps = blockDim.x >> 5;

    // ---- load keys + pre-normalized boxes into smem ----
    const float4* bb4 = (const float4*)(boxes + (size_t)b * NBOX * 4);
    for (int i = tid; i < NBOX; i += blockDim.x) {
        sk[i] = keys[b * NBOX + i];
        float4 r = bb4[i];
        float y1 = fminf(r.x, r.z), y2 = fmaxf(r.x, r.z);
        float x1 = fminf(r.y, r.w), x2 = fmaxf(r.y, r.w);
        sbox[i]  = make_float4(y1, x1, y2, x2);
        sarea[i] = (y2 - y1) * (x2 - x1);
    }
    if (tid == 0) { s_count = 0; s_stop = 0; }
    __syncthreads();

    // ---- bitonic sort, descending ----
    for (int seg = warp; seg < NBOX / 32; seg += nwarps) {
        const int i = (seg << 5) + lane;
        unsigned long long v = sk[i];
        #pragma unroll
        for (int k = 2; k <= 32; k <<= 1) {
            const bool desc = ((i & k) == 0);
            #pragma unroll
            for (int j = k >> 1; j >= 1; j >>= 1) {
                unsigned long long w = __shfl_xor_sync(FULL, v, j);
                bool upper   = (i & j) != 0;
                bool takeMax = desc ^ upper;
                v = takeMax ? (v > w ? v : w) : (v < w ? v : w);
            }
        }
        sk[i] = v;
    }
    __syncthreads();

    for (int k = 64; k <= NBOX; k <<= 1) {
        for (int j = k >> 1; j >= 32; j >>= 1) {
            for (int p = tid; p < NBOX / 2; p += blockDim.x) {
                int i = ((p & ~(j - 1)) << 1) | (p & (j - 1));
                int l = i | j;
                unsigned long long a = sk[i], c = sk[l];
                bool sw = ((i & k) == 0) ? (a < c) : (a > c);
                if (sw) { sk[i] = c; sk[l] = a; }
            }
            __syncthreads();
        }
        for (int seg = warp; seg < NBOX / 32; seg += nwarps) {
            const int i = (seg << 5) + lane;
            unsigned long long v = sk[i];
            const bool desc = ((i & k) == 0);
            #pragma unroll
            for (int j = 16; j >= 1; j >>= 1) {
                unsigned long long w = __shfl_xor_sync(FULL, v, j);
                bool upper   = (i & j) != 0;
                bool takeMax = desc ^ upper;
                v = takeMax ? (v > w ? v : w) : (v < w ? v : w);
            }
            sk[i] = v;
        }
        __syncthreads();
    }

    // ---- chunked NMS ----
    for (int r = 0; r < NBOX; r += CHUNK) {
        // phase 1: check every candidate vs kept set (4 threads/candidate)
        {
            const int cand = tid >> 2, sub = tid & 3;
            const unsigned long long key = sk[r + cand];
            const int idx = (int)(0xffffffffu - (unsigned)(key & 0xffffffffu));
            const float4 c  = sbox[idx];
            const float  ca = sarea[idx];
            const int    base = s_count;
            bool sup = false;
            for (int j = sub; j < base; j += 4) {
                float4 kb = kbox[j];
                float  ka = kar[j];
                float ih = fmaxf(0.0f, fminf(c.z, kb.z) - fmaxf(c.x, kb.x));
                float iw = fmaxf(0.0f, fminf(c.w, kb.w) - fmaxf(c.y, kb.y));
                float inter = ih * iw;
                float uni   = ca + ka - inter;
                float half  = 0.5f * uni;
                float diff  = inter - half;
                bool  s;
                if (fabsf(diff) <= half * 1e-5f) {      // borderline: exact
                    float iou = (inter > 0.0f) ? inter / uni : 0.0f;
                    s = iou > IOU_THR;
                } else {
                    s = (diff > 0.0f) && (inter > 0.0f);
                }
                sup |= s;
            }
            unsigned bal = __ballot_sync(FULL, sup);
            if (sub == 0)
                ssup[cand] = ((bal >> (lane & 28)) & 0xFu) ? 1 : 0;
        }
        __syncthreads();

        // phase 2: warp 0 resolves survivors in rank order
        if (warp == 0) {
            int count = s_count;
            int nk = 0;                                  // keeps this chunk
            float s0y1, s0x1, s0y2, s0x2, s0a;           // new-keep slots
            float s1y1, s1x1, s1y2, s1x2, s1a;
            float s2y1, s2x1, s2y2, s2x2, s2a;
            float s3y1, s3x1, s3y2, s3x2, s3a;
            bool stop_invalid = false;

            for (int g = 0; g < CHUNK / 32; g++) {
                const int ci = r + (g << 5) + lane;
                const unsigned long long key = sk[ci];
                const float score = __uint_as_float((unsigned)(key >> 32));
                const bool  validl = score > CONF_THR;
                const unsigned vm = __ballot_sync(FULL, validl);
                if (vm != FULL) stop_invalid = true;

                const bool alivel = validl && (ssup[(g << 5) + lane] == 0);
                unsigned m = __ballot_sync(FULL, alivel);
                if (m == 0) { if (count >= MAX_DET) break; continue; }

                const int idxl = (int)(0xffffffffu - (unsigned)(key & 0xffffffffu));
                const float4 cb = sbox[idxl];
                const float  cal = sarea[idxl];

                while (m && count < MAX_DET) {
                    const int i = __ffs(m) - 1;
                    m &= m - 1;
                    const float wy1 = __shfl_sync(FULL, cb.x, i);
                    const float wx1 = __shfl_sync(FULL, cb.y, i);
                    const float wy2 = __shfl_sync(FULL, cb.z, i);
                    const float wx2 = __shfl_sync(FULL, cb.w, i);
                    const float wa  = __shfl_sync(FULL, cal,  i);
                    const int   wi  = __shfl_sync(FULL, idxl, i);

                    bool s = false;
                    if (lane < nk) {
                        float ih = fmaxf(0.0f, fminf(wy2, s0y2) - fmaxf(wy1, s0y1));
                        float iw = fmaxf(0.0f, fminf(wx2, s0x2) - fmaxf(wx1, s0x1));
                        float inter = ih * iw;
                        float uni   = wa + s0a - inter;
                        float iou   = (inter > 0.0f) ? inter / uni : 0.0f;
                        s |= iou > IOU_THR;
                    }
                    if (nk > 32) {
                        if (lane + 32 < nk) {
                            float ih = fmaxf(0.0f, fminf(wy2, s1y2) - fmaxf(wy1, s1y1));
                            float iw = fmaxf(0.0f, fminf(wx2, s1x2) - fmaxf(wx1, s1x1));
                            float inter = ih * iw;
                            float uni   = wa + s1a - inter;
                            float iou   = (inter > 0.0f) ? inter / uni : 0.0f;
                            s |= iou > IOU_THR;
                        }
                        if (nk > 64 && lane + 64 < nk) {
                            float ih = fmaxf(0.0f, fminf(wy2, s2y2) - fmaxf(wy1, s2y1));
                            float iw = fmaxf(0.0f, fminf(wx2, s2x2) - fmaxf(wx1, s2x1));
                            float inter = ih * iw;
                            float uni   = wa + s2a - inter;
                            float iou   = (inter > 0.0f) ? inter / uni : 0.0f;
                            s |= iou > IOU_THR;
                        }
                        if (nk > 96 && lane + 96 < nk) {
                            float ih = fmaxf(0.0f, fminf(wy2, s3y2) - fmaxf(wy1, s3y1));
                            float iw = fmaxf(0.0f, fminf(wx2, s3x2) - fmaxf(wx1, s3x1));
                            float inter = ih * iw;
                            float uni   = wa + s3a - inter;
                            float iou   = (inter > 0.0f) ? inter / uni : 0.0f;
                            s |= iou > IOU_THR;
                        }
                    }
                    if (__ballot_sync(FULL, s) == 0u) {       // keep it
                        const int t = nk >> 5;
                        if (lane == (nk & 31)) {
                            if      (t == 0) { s0y1=wy1; s0x1=wx1; s0y2=wy2; s0x2=wx2; s0a=wa; }
                            else if (t == 1) { s1y1=wy1; s1x1=wx1; s1y2=wy2; s1x2=wx2; s1a=wa; }
                            else if (t == 2) { s2y1=wy1; s2x1=wx1; s2y2=wy2; s2x2=wx2; s2a=wa; }
                            else             { s3y1=wy1; s3x1=wx1; s3y2=wy2; s3x2=wx2; s3a=wa; }
                        }
                        if (lane == 0) {
                            kbox[count] = make_float4(wy1, wx1, wy2, wx2);
                            kar[count]  = wa;
                            kidx[count] = wi;
                        }
                        count++; nk++;
                    }
                }
                if (count >= MAX_DET) break;
            }
            if (lane == 0) {
                s_count = count;
                s_stop  = (count >= MAX_DET) || stop_invalid;
            }
        }
        __syncthreads();
        if (s_stop) break;
    }

    const int count = s_count;

    // ---- outputs (zero-pad beyond count) ----
    float* ob = nms_box + (size_t)b * MAX_DET * 4;
    for (int t = tid; t < MAX_DET * 4; t += blockDim.x) {
        int k = t >> 2, c = t & 3;
        ob[t] = (k < count)
              ? boxes[(size_t)b * NBOX * 4 + (size_t)kidx[k] * 4 + c]
              : 0.0f;
    }
    float* oc = nms_cls + (size_t)b * MAX_DET * NCLS;
    for (int t = tid; t < MAX_DET * NCLS; t += blockDim.x) {
        int k = t / NCLS, c = t % NCLS;
        oc[t] = (k < count)
              ? cls_soft[((size_t)b * NBOX + (size_t)kidx[k]) * NCLS + c]
              : 0.0f;
    }
}

// ---------------------------------------------------------------------------
extern "C" void kernel_launch(void* const* d_in, const int* in_sizes, int n_in,
                              void* d_out, int out_size)
{
    const float* boxes;
    const float* cls;
    if (in_sizes[0] == BATCH * NBOX * 4) {
        boxes = (const float*)d_in[0];
        cls   = (const float*)d_in[1];
    } else {
        boxes = (const float*)d_in[1];
        cls   = (const float*)d_in[0];
    }

    float* out      = (float*)d_out;
    float* nms_box  = out;                                  // [16,100,4]
    float* nms_cls  = out + BATCH * MAX_DET * 4;            // [16,100,80]
    float* cls_pred = out + BATCH * MAX_DET * 4
                          + BATCH * MAX_DET * NCLS;         // [16,4096,80]

    unsigned long long* keys = nullptr;
    cudaGetSymbolAddress((void**)&keys, g_keys);

    const int DYN_SMEM = NBOX * (int)sizeof(float4)
                       + NBOX * (int)sizeof(unsigned long long)
                       + NBOX * (int)sizeof(float);         // 112 KB
    static int smem_set = 0;
    if (!smem_set) {
        cudaFuncSetAttribute(nms_kernel,
                             cudaFuncAttributeMaxDynamicSharedMemorySize,
                             DYN_SMEM);
        smem_set = 1;
    }

    const int rows = BATCH * NBOX;
    softmax_key_kernel<<<rows / 8, 256>>>(cls, cls_pred, keys);
    nms_kernel<<<BATCH, 1024, DYN_SMEM>>>(boxes, cls_pred, keys, nms_box, nms_cls);
}

// round 7
// speedup vs baseline: 4.2638x; 2.0413x over previous
#include <cuda_runtime.h>
#include <stdint.h>

#define BATCH    16
#define NBOX     4096
#define NCLS     80
#define MAX_DET  100
#define IOU_THR  0.5f
#define CONF_THR 0.5f
#define FULL     0xffffffffu
#define CHUNK    128
#define SUBS     8                  // 1024 threads / 128 candidates
#define NW       (CHUNK / 32)       // 4 alive-mask words

// scratch: per-row sort keys  (score_bits << 32) | (0xFFFFFFFF - idx)
__device__ unsigned long long g_keys[BATCH * NBOX];

// guarded IoU>0.5 test: cheap compare with exact-divide fallback in a narrow
// borderline band (validated in earlier passing rounds).
__device__ __forceinline__ bool iou_gt(float y1a, float x1a, float y2a, float x2a, float aa,
                                       float y1b, float x1b, float y2b, float x2b, float ab)
{
    float ih = fmaxf(0.0f, fminf(y2a, y2b) - fmaxf(y1a, y1b));
    float iw = fmaxf(0.0f, fminf(x2a, x2b) - fmaxf(x1a, x1b));
    float inter = ih * iw;
    float uni   = aa + ab - inter;
    float half  = 0.5f * uni;
    float diff  = inter - half;
    if (fabsf(diff) <= half * 1e-5f) {          // borderline: exact semantics
        float iou = (inter > 0.0f) ? inter / uni : 0.0f;
        return iou > IOU_THR;
    }
    return (diff > 0.0f) && (inter > 0.0f);
}

// ---------------------------------------------------------------------------
// Kernel 1: softmax(square(x*10)) per row, write cls_predictions, emit keys.
// ---------------------------------------------------------------------------
__global__ void __launch_bounds__(256)
softmax_key_kernel(const float* __restrict__ cls_in,
                   float* __restrict__ cls_out,
                   unsigned long long* __restrict__ keys)
{
    const int lane = threadIdx.x & 31;
    const int row  = blockIdx.x * (blockDim.x >> 5) + (threadIdx.x >> 5);
    if (row >= BATCH * NBOX) return;

    const float* in = cls_in + (size_t)row * NCLS;

    const bool has2 = lane < (NCLS - 64);
    float x0 = in[lane]      * 10.0f;
    float x1 = in[lane + 32] * 10.0f;
    float x2 = has2 ? in[lane + 64] * 10.0f : 0.0f;
    float a0 = x0 * x0, a1 = x1 * x1, a2 = x2 * x2;

    float amax = fmaxf(a0, a1);
    if (has2) amax = fmaxf(amax, a2);
    #pragma unroll
    for (int o = 16; o; o >>= 1)
        amax = fmaxf(amax, __shfl_xor_sync(FULL, amax, o));

    float e0 = expf(a0 - amax);
    float e1 = expf(a1 - amax);
    float e2 = has2 ? expf(a2 - amax) : 0.0f;

    float s = e0 + e1 + e2;
    #pragma unroll
    for (int o = 16; o; o >>= 1)
        s += __shfl_xor_sync(FULL, s, o);

    const float recip = 1.0f / s;
    float o0 = e0 * recip, o1 = e1 * recip, o2 = e2 * recip;

    float* out = cls_out + (size_t)row * NCLS;
    out[lane]      = o0;
    out[lane + 32] = o1;
    if (has2) out[lane + 64] = o2;

    float m = fmaxf(o0, o1);
    if (has2) m = fmaxf(m, o2);
    #pragma unroll
    for (int o = 16; o; o >>= 1)
        m = fmaxf(m, __shfl_xor_sync(FULL, m, o));

    if (lane == 0) {
        const unsigned n = (unsigned)(row & (NBOX - 1));
        keys[row] = ((unsigned long long)__float_as_uint(m) << 32)
                  | (unsigned long long)(0xffffffffu - n);
    }
}

// ---------------------------------------------------------------------------
// Kernel 2: sort + bitmap-chunked NMS.
//   Phase A (all threads): vs-kept check + intra-chunk 128x128 suppression matrix
//   Phase B (thread 0)   : bit-scan propagation, work proportional to KEEPS only
// Dynamic smem: float4 sbox[NBOX] | u64 sk[NBOX] | float sarea[NBOX]  (112KB)
// ---------------------------------------------------------------------------
__global__ void __launch_bounds__(1024, 1)
nms_kernel(const float* __restrict__ boxes,        // [B,N,4]
           const float* __restrict__ cls_soft,     // [B,N,C]
           const unsigned long long* __restrict__ keys,
           float* __restrict__ nms_box,            // [B,MAX_DET,4]
           float* __restrict__ nms_cls)            // [B,MAX_DET,C]
{
    extern __shared__ char dyn[];
    float4*             sbox  = (float4*)dyn;                       // 64KB
    unsigned long long* sk    = (unsigned long long*)(sbox + NBOX); // 32KB
    float*              sarea = (float*)(sk + NBOX);                // 16KB

    __shared__ float4        kbox[MAX_DET];     // kept set (all prev chunks)
    __shared__ float         kar[MAX_DET];
    __shared__ int           kidx[MAX_DET];
    __shared__ float4        cbox[CHUNK];       // staged chunk
    __shared__ float         car[CHUNK];
    __shared__ int           cidx[CHUNK];
    __shared__ unsigned char ssup[CHUNK];       // suppressed by kept set (0/1)
    __shared__ unsigned      validw[NW];        // validity ballots
    __shared__ __align__(16) unsigned short mat16[CHUNK][SUBS];  // 2KB matrix
    __shared__ int s_count, s_stop;

    const int b    = blockIdx.x;
    const int tid  = threadIdx.x;
    const int lane = tid & 31;
    const int warp = tid >> 5;
    const int nwarps = blockDim.x >> 5;

    // ---- load keys + pre-normalized boxes into smem ----
    const float4* bb4 = (const float4*)(boxes + (size_t)b * NBOX * 4);
    for (int i = tid; i < NBOX; i += blockDim.x) {
        sk[i] = keys[b * NBOX + i];
        float4 r = bb4[i];
        float y1 = fminf(r.x, r.z), y2 = fmaxf(r.x, r.z);
        float x1 = fminf(r.y, r.w), x2 = fmaxf(r.y, r.w);
        sbox[i]  = make_float4(y1, x1, y2, x2);
        sarea[i] = (y2 - y1) * (x2 - x1);
    }
    if (tid == 0) { s_count = 0; s_stop = 0; }
    __syncthreads();

    // ---- bitonic sort, descending ----
    for (int seg = warp; seg < NBOX / 32; seg += nwarps) {
        const int i = (seg << 5) + lane;
        unsigned long long v = sk[i];
        #pragma unroll
        for (int k = 2; k <= 32; k <<= 1) {
            const bool desc = ((i & k) == 0);
            #pragma unroll
            for (int j = k >> 1; j >= 1; j >>= 1) {
                unsigned long long w = __shfl_xor_sync(FULL, v, j);
                bool upper   = (i & j) != 0;
                bool takeMax = desc ^ upper;
                v = takeMax ? (v > w ? v : w) : (v < w ? v : w);
            }
        }
        sk[i] = v;
    }
    __syncthreads();

    for (int k = 64; k <= NBOX; k <<= 1) {
        for (int j = k >> 1; j >= 32; j >>= 1) {
            for (int p = tid; p < NBOX / 2; p += blockDim.x) {
                int i = ((p & ~(j - 1)) << 1) | (p & (j - 1));
                int l = i | j;
                unsigned long long a = sk[i], c = sk[l];
                bool sw = ((i & k) == 0) ? (a < c) : (a > c);
                if (sw) { sk[i] = c; sk[l] = a; }
            }
            __syncthreads();
        }
        for (int seg = warp; seg < NBOX / 32; seg += nwarps) {
            const int i = (seg << 5) + lane;
            unsigned long long v = sk[i];
            const bool desc = ((i & k) == 0);
            #pragma unroll
            for (int j = 16; j >= 1; j >>= 1) {
                unsigned long long w = __shfl_xor_sync(FULL, v, j);
                bool upper   = (i & j) != 0;
                bool takeMax = desc ^ upper;
                v = takeMax ? (v > w ? v : w) : (v < w ? v : w);
            }
            sk[i] = v;
        }
        __syncthreads();
    }

    // ---- bitmap-chunked NMS ----
    for (int r = 0; r < NBOX; r += CHUNK) {
        // stage chunk: boxes, areas, indices, validity ballots
        if (tid < CHUNK) {
            const unsigned long long key = sk[r + tid];
            const float score = __uint_as_float((unsigned)(key >> 32));
            const int   idx = (int)(0xffffffffu - (unsigned)(key & 0xffffffffu));
            cidx[tid] = idx;
            cbox[tid] = sbox[idx];
            car[tid]  = sarea[idx];
            unsigned vb = __ballot_sync(FULL, score > CONF_THR);
            if ((tid & 31) == 0) validw[tid >> 5] = vb;
        }
        __syncthreads();

        // Phase A: all 1024 threads
        {
            const int cand = tid >> 3, sub = tid & 7;
            const float4 c  = cbox[cand];
            const float  ca = car[cand];

            // A1: candidate vs kept set (stride-8, fixed trip)
            const int cnt = s_count;
            bool sup = false;
            for (int j = sub; j < cnt; j += SUBS) {
                float4 kb = kbox[j];
                sup |= iou_gt(c.x, c.y, c.z, c.w, ca,
                              kb.x, kb.y, kb.z, kb.w, kar[j]);
            }
            unsigned bal = __ballot_sync(FULL, sup);
            if (sub == 0)
                ssup[cand] = ((bal >> (lane & 24)) & 0xFFu) ? 1 : 0;

            // A2: intra-chunk matrix row bits for j in [sub*16, sub*16+16), j>cand
            unsigned bits = 0;
            const int j0 = sub << 4;
            if (j0 + 15 > cand) {
                #pragma unroll
                for (int t = 0; t < 16; t++) {
                    const int j = j0 + t;
                    if (j > cand) {
                        float4 d = cbox[j];
                        if (iou_gt(c.x, c.y, c.z, c.w, ca,
                                   d.x, d.y, d.z, d.w, car[j]))
                            bits |= (1u << t);
                    }
                }
            }
            mat16[cand][sub] = (unsigned short)bits;
        }
        __syncthreads();

        // Phase B: thread 0 propagates; visits kept candidates only
        if (tid == 0) {
            const unsigned* ss32 = (const unsigned*)ssup;
            unsigned aw[NW];
            bool any_invalid = false;
            #pragma unroll
            for (int w = 0; w < NW; w++) {
                unsigned v = validw[w];
                if (v != FULL) any_invalid = true;
                unsigned supb = 0;
                #pragma unroll
                for (int q = 0; q < 8; q++) {          // 4 bytes -> 4 bits
                    unsigned x = ss32[w * 8 + q];
                    unsigned nib = (x & 1u) | ((x >> 7) & 2u)
                                 | ((x >> 14) & 4u) | ((x >> 21) & 8u);
                    supb |= nib << (q * 4);
                }
                aw[w] = v & ~supb;
            }

            int count = s_count;
            #pragma unroll
            for (int w = 0; w < NW; w++) {
                while (aw[w] && count < MAX_DET) {
                    const int bit = __ffs(aw[w]) - 1;
                    const int i = (w << 5) + bit;
                    aw[w] &= aw[w] - 1;
                    // keep i
                    kbox[count] = cbox[i];
                    kar[count]  = car[i];
                    kidx[count] = cidx[i];
                    count++;
                    // suppress later candidates in this chunk
                    const uint4 row = *(const uint4*)&mat16[i][0];
                    aw[0] &= ~row.x; aw[1] &= ~row.y;
                    aw[2] &= ~row.z; aw[3] &= ~row.w;
                }
                if (count >= MAX_DET) break;
            }
            s_count = count;
            s_stop  = (count >= MAX_DET) || any_invalid;
        }
        __syncthreads();
        if (s_stop) break;
    }

    const int count = s_count;

    // ---- outputs (zero-pad beyond count) ----
    float* ob = nms_box + (size_t)b * MAX_DET * 4;
    for (int t = tid; t < MAX_DET * 4; t += blockDim.x) {
        int k = t >> 2, c = t & 3;
        ob[t] = (k < count)
              ? boxes[(size_t)b * NBOX * 4 + (size_t)kidx[k] * 4 + c]
              : 0.0f;
    }
    float* oc = nms_cls + (size_t)b * MAX_DET * NCLS;
    for (int t = tid; t < MAX_DET * NCLS; t += blockDim.x) {
        int k = t / NCLS, c = t % NCLS;
        oc[t] = (k < count)
              ? cls_soft[((size_t)b * NBOX + (size_t)kidx[k]) * NCLS + c]
              : 0.0f;
    }
}

// ---------------------------------------------------------------------------
extern "C" void kernel_launch(void* const* d_in, const int* in_sizes, int n_in,
                              void* d_out, int out_size)
{
    const float* boxes;
    const float* cls;
    if (in_sizes[0] == BATCH * NBOX * 4) {
        boxes = (const float*)d_in[0];
        cls   = (const float*)d_in[1];
    } else {
        boxes = (const float*)d_in[1];
        cls   = (const float*)d_in[0];
    }

    float* out      = (float*)d_out;
    float* nms_box  = out;                                  // [16,100,4]
    float* nms_cls  = out + BATCH * MAX_DET * 4;            // [16,100,80]
    float* cls_pred = out + BATCH * MAX_DET * 4
                          + BATCH * MAX_DET * NCLS;         // [16,4096,80]

    unsigned long long* keys = nullptr;
    cudaGetSymbolAddress((void**)&keys, g_keys);

    const int DYN_SMEM = NBOX * (int)sizeof(float4)
                       + NBOX * (int)sizeof(unsigned long long)
                       + NBOX * (int)sizeof(float);         // 112 KB
    static int smem_set = 0;
    if (!smem_set) {
        cudaFuncSetAttribute(nms_kernel,
                             cudaFuncAttributeMaxDynamicSharedMemorySize,
                             DYN_SMEM);
        smem_set = 1;
    }

    const int rows = BATCH * NBOX;
    softmax_key_kernel<<<rows / 8, 256>>>(cls, cls_pred, keys);
    nms_kernel<<<BATCH, 1024, DYN_SMEM>>>(boxes, cls_pred, keys, nms_box, nms_cls);
}